// round 4
// baseline (speedup 1.0000x reference)
#include <cuda_runtime.h>
#include <math.h>

// Closed-form reduction of the 4-qubit circuit:
//   z = cosB * cos(t1)cos(t2)cos(t3) - sinB*cos(phi0)*cos(phi1) * sin(t0)sin(t1)
//   t_i = tanh(W1[i]*x + b1[i]) + qw[0,i],  |t_i| < ~1.5
// Single kernel, 1 sample/thread, no smem/barrier: params are uniform-address
// LDGs (warp-broadcast, L1-hit after first blocks); derived trig constants are
// recomputed per-thread with FMA-pipe Taylor polys (|qw| ~ 0.1).

__device__ __forceinline__ float tanh_from_scaled(float q) {
    // tanh(p) where q = 2*log2(e)*p: tanh = 1 - 2/(exp2(q)+1)
    float e;
    asm("ex2.approx.f32 %0, %1;" : "=f"(e) : "f"(q));
    float d = e + 1.0f;
    float r;
    asm("rcp.approx.f32 %0, %1;" : "=f"(r) : "f"(d));
    return fmaf(-2.0f, r, 1.0f);
}

// sin(x), |x| <= ~1.6 : deg-9 Taylor, abs err < 2e-6 at 1.5
__device__ __forceinline__ float sin_poly(float x, float y /* = x*x */) {
    float p = fmaf(y, 2.7557319e-6f, -1.9841270e-4f);
    p = fmaf(y, p, 8.3333333e-3f);
    p = fmaf(y, p, -1.6666667e-1f);
    p = fmaf(y, p, 1.0f);
    return x * p;
}

// cos(x), |x| <= ~1.6 : deg-8 Taylor, abs err < 2e-5 at 1.5
__device__ __forceinline__ float cos_poly(float y /* = x*x */) {
    float p = fmaf(y, 2.4801587e-5f, -1.3888889e-3f);
    p = fmaf(y, p, 4.1666667e-2f);
    p = fmaf(y, p, -5.0e-1f);
    p = fmaf(y, p, 1.0f);
    return p;
}

__global__ __launch_bounds__(256) void qnn_fused(
    const float4* __restrict__ x, float2* __restrict__ out,
    const float4* __restrict__ W1, const float4* __restrict__ b1,
    const float4* __restrict__ qw, const float4* __restrict__ W2,
    const float4* __restrict__ b2, const float4* __restrict__ W3,
    const float* __restrict__ b3, int n)
{
    int i = blockIdx.x * blockDim.x + threadIdx.x;
    if (i >= n) return;

    // Payload load first: fills DRAM latency with param loads + derived math.
    float4 xv = x[i];

    // Uniform-address param loads (warp-broadcast, 1 wavefront each).
    float4 w0 = W1[0], w1 = W1[1], w2 = W1[2], w3 = W1[3];
    float4 bb = b1[0];               // first 4 of 8 (rows 4..7 unused)
    float4 off = qw[0];              // qw[0,*] angle offsets
    float4 phi = qw[1];              // qw[1,*]
    float4 qr2 = qw[2];              // beta = qr2.x = qw[2,0]
    float4 W2v = W2[0], b2v = b2[0];
    float4 W3a = W3[0], W3b = W3[1];
    float  b3x = b3[0], b3y = b3[1];

    // Derived constants (per-thread, FMA pipe; |qw| small so Taylor is exact
    // to ~1e-9 here).
    float beta = qr2.x;
    float yb = beta * beta;
    float cB = cos_poly(yb);
    float sB = sin_poly(beta, yb);
    float c2 = sB * cos_poly(phi.x * phi.x) * cos_poly(phi.y * phi.y);

    const float S = 2.0f * 1.4426950408889634f;  // 2*log2(e)

    // Pre-layer dot products (rows 0..3 of W1 only).
    float q0 = fmaf(w0.x, xv.x, fmaf(w0.y, xv.y, fmaf(w0.z, xv.z, fmaf(w0.w, xv.w, bb.x))));
    float q1 = fmaf(w1.x, xv.x, fmaf(w1.y, xv.y, fmaf(w1.z, xv.z, fmaf(w1.w, xv.w, bb.y))));
    float q2 = fmaf(w2.x, xv.x, fmaf(w2.y, xv.y, fmaf(w2.z, xv.z, fmaf(w2.w, xv.w, bb.z))));
    float q3 = fmaf(w3.x, xv.x, fmaf(w3.y, xv.y, fmaf(w3.z, xv.z, fmaf(w3.w, xv.w, bb.w))));

    float t0 = tanh_from_scaled(S * q0) + off.x;
    float t1 = tanh_from_scaled(S * q1) + off.y;
    float t2 = tanh_from_scaled(S * q2) + off.z;
    float t3 = tanh_from_scaled(S * q3) + off.w;

    float y0 = t0 * t0, y1 = t1 * t1, y2 = t2 * t2, y3 = t3 * t3;

    float st0 = sin_poly(t0, y0);
    float st1 = sin_poly(t1, y1);
    float ct1 = cos_poly(y1);
    float ct2 = cos_poly(y2);
    float ct3 = cos_poly(y3);

    float z = cB * (ct1 * ct2 * ct3) - c2 * (st0 * st1);

    // Post-layer: relu(z*W2 + b2) @ W3^T + b3
    float g0 = fmaxf(fmaf(W2v.x, z, b2v.x), 0.0f);
    float g1 = fmaxf(fmaf(W2v.y, z, b2v.y), 0.0f);
    float g2 = fmaxf(fmaf(W2v.z, z, b2v.z), 0.0f);
    float g3 = fmaxf(fmaf(W2v.w, z, b2v.w), 0.0f);

    float o0 = fmaf(W3a.x, g0, fmaf(W3a.y, g1, fmaf(W3a.z, g2, fmaf(W3a.w, g3, b3x))));
    float o1 = fmaf(W3b.x, g0, fmaf(W3b.y, g1, fmaf(W3b.z, g2, fmaf(W3b.w, g3, b3y))));

    out[i] = make_float2(o0, o1);
}

extern "C" void kernel_launch(void* const* d_in, const int* in_sizes, int n_in,
                              void* d_out, int out_size) {
    const float* x  = (const float*)d_in[0];
    const float* W1 = (const float*)d_in[1];
    const float* b1 = (const float*)d_in[2];
    const float* qw = (const float*)d_in[3];
    const float* W2 = (const float*)d_in[4];
    const float* b2 = (const float*)d_in[5];
    const float* W3 = (const float*)d_in[6];
    const float* b3 = (const float*)d_in[7];

    int n = in_sizes[0] / 4;   // batch size
    int threads = 256;
    int blocks = (n + threads - 1) / threads;

    qnn_fused<<<blocks, threads>>>(reinterpret_cast<const float4*>(x),
                                   reinterpret_cast<float2*>(d_out),
                                   reinterpret_cast<const float4*>(W1),
                                   reinterpret_cast<const float4*>(b1),
                                   reinterpret_cast<const float4*>(qw),
                                   reinterpret_cast<const float4*>(W2),
                                   reinterpret_cast<const float4*>(b2),
                                   reinterpret_cast<const float4*>(W3),
                                   b3, n);
}

// round 6
// speedup vs baseline: 1.0487x; 1.0487x over previous
#include <cuda_runtime.h>
#include <math.h>

// Closed-form reduction of the 4-qubit circuit:
//   z = cosB * cos(t1)cos(t2)cos(t3) - sinB*cos(phi0)*cos(phi1) * sin(t0)sin(t1)
//   t_i = tanh(W1[i]*x + b1[i]) + qw[0,i]
// Single kernel, 1 sample/thread, no smem/barrier/second launch. Params are
// uniform-address LDGs (warp-broadcast, L1-hit after first blocks); the 4
// derived trig constants use MUFU (1 slot each) per thread.

__device__ __forceinline__ float tanh_fast(float p) {
    // tanh(p) = 1 - 2/(exp2(2*log2e*p)+1)
    float q = p * 2.8853900817779268f;  // 2*log2(e)
    float e;
    asm("ex2.approx.f32 %0, %1;" : "=f"(e) : "f"(q));
    float d = e + 1.0f;
    float r;
    asm("rcp.approx.f32 %0, %1;" : "=f"(r) : "f"(d));
    return fmaf(-2.0f, r, 1.0f);
}

__global__ __launch_bounds__(256) void qnn_kernel(
    const float4* __restrict__ x, float2* __restrict__ out,
    const float4* __restrict__ W1, const float4* __restrict__ b1,
    const float4* __restrict__ qw, const float4* __restrict__ W2,
    const float4* __restrict__ b2, const float4* __restrict__ W3,
    const float2* __restrict__ b3, int n)
{
    int i = blockIdx.x * blockDim.x + threadIdx.x;
    if (i >= n) return;

    // Payload load first; param loads + derived math fill its latency shadow.
    float4 xv = x[i];

    // Uniform-address param loads (single-wavefront broadcasts).
    float4 w0 = W1[0], w1 = W1[1], w2 = W1[2], w3 = W1[3];
    float4 bb = b1[0];               // rows 4..7 of W1/b1 unused downstream
    float4 off = qw[0];              // qw[0,*] angle offsets
    float4 phi = qw[1];              // phi0=qw[1,0], phi1=qw[1,1]
    float4 qr2 = qw[2];              // beta = qw[2,0]
    float4 W2v = W2[0], b2v = b2[0];
    float4 W3a = W3[0], W3b = W3[1];
    float2 b3v = b3[0];

    // Derived constants via MUFU (4 ops + 2 muls).
    float beta = qr2.x;
    float cB = __cosf(beta);
    float c2 = __sinf(beta) * __cosf(phi.x) * __cosf(phi.y);

    // Pre-layer dot products (rows 0..3 of W1 only).
    float q0 = fmaf(w0.x, xv.x, fmaf(w0.y, xv.y, fmaf(w0.z, xv.z, fmaf(w0.w, xv.w, bb.x))));
    float q1 = fmaf(w1.x, xv.x, fmaf(w1.y, xv.y, fmaf(w1.z, xv.z, fmaf(w1.w, xv.w, bb.y))));
    float q2 = fmaf(w2.x, xv.x, fmaf(w2.y, xv.y, fmaf(w2.z, xv.z, fmaf(w2.w, xv.w, bb.z))));
    float q3 = fmaf(w3.x, xv.x, fmaf(w3.y, xv.y, fmaf(w3.z, xv.z, fmaf(w3.w, xv.w, bb.w))));

    float t0 = tanh_fast(q0) + off.x;
    float t1 = tanh_fast(q1) + off.y;
    float t2 = tanh_fast(q2) + off.z;
    float t3 = tanh_fast(q3) + off.w;

    float st0 = __sinf(t0);
    float st1 = __sinf(t1);
    float ct1 = __cosf(t1);
    float ct2 = __cosf(t2);
    float ct3 = __cosf(t3);

    float z = cB * (ct1 * ct2 * ct3) - c2 * (st0 * st1);

    // Post-layer: relu(z*W2 + b2) @ W3^T + b3
    float g0 = fmaxf(fmaf(W2v.x, z, b2v.x), 0.0f);
    float g1 = fmaxf(fmaf(W2v.y, z, b2v.y), 0.0f);
    float g2 = fmaxf(fmaf(W2v.z, z, b2v.z), 0.0f);
    float g3 = fmaxf(fmaf(W2v.w, z, b2v.w), 0.0f);

    float o0 = fmaf(W3a.x, g0, fmaf(W3a.y, g1, fmaf(W3a.z, g2, fmaf(W3a.w, g3, b3v.x))));
    float o1 = fmaf(W3b.x, g0, fmaf(W3b.y, g1, fmaf(W3b.z, g2, fmaf(W3b.w, g3, b3v.y))));

    out[i] = make_float2(o0, o1);
}

extern "C" void kernel_launch(void* const* d_in, const int* in_sizes, int n_in,
                              void* d_out, int out_size) {
    const float* x  = (const float*)d_in[0];
    const float* W1 = (const float*)d_in[1];
    const float* b1 = (const float*)d_in[2];
    const float* qw = (const float*)d_in[3];
    const float* W2 = (const float*)d_in[4];
    const float* b2 = (const float*)d_in[5];
    const float* W3 = (const float*)d_in[6];
    const float* b3 = (const float*)d_in[7];

    int n = in_sizes[0] / 4;   // batch size
    int threads = 256;
    int blocks = (n + threads - 1) / threads;

    qnn_kernel<<<blocks, threads>>>(reinterpret_cast<const float4*>(x),
                                    reinterpret_cast<float2*>(d_out),
                                    reinterpret_cast<const float4*>(W1),
                                    reinterpret_cast<const float4*>(b1),
                                    reinterpret_cast<const float4*>(qw),
                                    reinterpret_cast<const float4*>(W2),
                                    reinterpret_cast<const float4*>(b2),
                                    reinterpret_cast<const float4*>(W3),
                                    reinterpret_cast<const float2*>(b3), n);
}

// round 7
// speedup vs baseline: 1.2470x; 1.1890x over previous
#include <cuda_runtime.h>
#include <math.h>

// Closed-form reduction of the 4-qubit circuit:
//   z = cosB * cos(t1)cos(t2)cos(t3) - sinB*cos(phi0)*cos(phi1) * sin(t0)sin(t1)
//   t_i = tanh(W1[i]*x + b1[i]) + qw[0,i]
// Single kernel, 2 samples/thread (lane-transposed), no smem/barrier.
// Params are uniform-address LDGs (warp-broadcast) loaded once per thread;
// derived trig constants via MUFU. Both x loads issued back-to-back (MLP=2).

__device__ __forceinline__ float tanh_fast(float p) {
    // tanh(p) = 1 - 2/(exp2(2*log2e*p)+1)
    float q = p * 2.8853900817779268f;  // 2*log2(e)
    float e;
    asm("ex2.approx.f32 %0, %1;" : "=f"(e) : "f"(q));
    float d = e + 1.0f;
    float r;
    asm("rcp.approx.f32 %0, %1;" : "=f"(r) : "f"(d));
    return fmaf(-2.0f, r, 1.0f);
}

struct PP {
    float4 w0, w1, w2, w3, bb, off;
    float4 W2v, b2v, W3a, W3b;
    float2 b3v;
    float cB, c2;
};

__device__ __forceinline__ float2 sample_eval(const PP& p, float4 xv) {
    float q0 = fmaf(p.w0.x, xv.x, fmaf(p.w0.y, xv.y, fmaf(p.w0.z, xv.z, fmaf(p.w0.w, xv.w, p.bb.x))));
    float q1 = fmaf(p.w1.x, xv.x, fmaf(p.w1.y, xv.y, fmaf(p.w1.z, xv.z, fmaf(p.w1.w, xv.w, p.bb.y))));
    float q2 = fmaf(p.w2.x, xv.x, fmaf(p.w2.y, xv.y, fmaf(p.w2.z, xv.z, fmaf(p.w2.w, xv.w, p.bb.z))));
    float q3 = fmaf(p.w3.x, xv.x, fmaf(p.w3.y, xv.y, fmaf(p.w3.z, xv.z, fmaf(p.w3.w, xv.w, p.bb.w))));

    float t0 = tanh_fast(q0) + p.off.x;
    float t1 = tanh_fast(q1) + p.off.y;
    float t2 = tanh_fast(q2) + p.off.z;
    float t3 = tanh_fast(q3) + p.off.w;

    float st0 = __sinf(t0);
    float st1 = __sinf(t1);
    float ct1 = __cosf(t1);
    float ct2 = __cosf(t2);
    float ct3 = __cosf(t3);

    float z = p.cB * (ct1 * ct2 * ct3) - p.c2 * (st0 * st1);

    float g0 = fmaxf(fmaf(p.W2v.x, z, p.b2v.x), 0.0f);
    float g1 = fmaxf(fmaf(p.W2v.y, z, p.b2v.y), 0.0f);
    float g2 = fmaxf(fmaf(p.W2v.z, z, p.b2v.z), 0.0f);
    float g3 = fmaxf(fmaf(p.W2v.w, z, p.b2v.w), 0.0f);

    float o0 = fmaf(p.W3a.x, g0, fmaf(p.W3a.y, g1, fmaf(p.W3a.z, g2, fmaf(p.W3a.w, g3, p.b3v.x))));
    float o1 = fmaf(p.W3b.x, g0, fmaf(p.W3b.y, g1, fmaf(p.W3b.z, g2, fmaf(p.W3b.w, g3, p.b3v.y))));
    return make_float2(o0, o1);
}

__global__ __launch_bounds__(256) void qnn_kernel(
    const float4* __restrict__ x, float2* __restrict__ out,
    const float4* __restrict__ W1, const float4* __restrict__ b1,
    const float4* __restrict__ qw, const float4* __restrict__ W2,
    const float4* __restrict__ b2, const float4* __restrict__ W3,
    const float2* __restrict__ b3, int n)
{
    // Block handles 512 consecutive samples, lane-transposed for coalescing.
    int i0 = blockIdx.x * 512 + threadIdx.x;
    int i1 = i0 + 256;

    // Both payload loads issued back-to-back first (MLP=2).
    float4 xa = make_float4(0, 0, 0, 0), xb = xa;
    bool a0 = (i0 < n), a1 = (i1 < n);
    if (a0) xa = x[i0];
    if (a1) xb = x[i1];

    // Uniform-address param loads (single-wavefront broadcasts, L1-hit after
    // the first blocks) — amortized over 2 samples.
    PP p;
    p.w0 = W1[0]; p.w1 = W1[1]; p.w2 = W1[2]; p.w3 = W1[3];
    p.bb = b1[0];                 // rows 4..7 of W1/b1 unused downstream
    p.off = qw[0];                // qw[0,*]
    float4 phi = qw[1];
    float4 qr2 = qw[2];           // beta = qw[2,0]
    p.W2v = W2[0]; p.b2v = b2[0];
    p.W3a = W3[0]; p.W3b = W3[1];
    p.b3v = b3[0];

    float beta = qr2.x;
    p.cB = __cosf(beta);
    p.c2 = __sinf(beta) * __cosf(phi.x) * __cosf(phi.y);

    if (a0) {
        float2 r = sample_eval(p, xa);
        out[i0] = r;
    }
    if (a1) {
        float2 r = sample_eval(p, xb);
        out[i1] = r;
    }
}

extern "C" void kernel_launch(void* const* d_in, const int* in_sizes, int n_in,
                              void* d_out, int out_size) {
    const float* x  = (const float*)d_in[0];
    const float* W1 = (const float*)d_in[1];
    const float* b1 = (const float*)d_in[2];
    const float* qw = (const float*)d_in[3];
    const float* W2 = (const float*)d_in[4];
    const float* b2 = (const float*)d_in[5];
    const float* W3 = (const float*)d_in[6];
    const float* b3 = (const float*)d_in[7];

    int n = in_sizes[0] / 4;   // batch size
    int blocks = (n + 511) / 512;

    qnn_kernel<<<blocks, 256>>>(reinterpret_cast<const float4*>(x),
                                reinterpret_cast<float2*>(d_out),
                                reinterpret_cast<const float4*>(W1),
                                reinterpret_cast<const float4*>(b1),
                                reinterpret_cast<const float4*>(qw),
                                reinterpret_cast<const float4*>(W2),
                                reinterpret_cast<const float4*>(b2),
                                reinterpret_cast<const float4*>(W3),
                                reinterpret_cast<const float2*>(b3), n);
}